// round 1
// baseline (speedup 1.0000x reference)
#include <cuda_runtime.h>
#include <cstdint>

#define BB 32
#define CC 128
#define HH 56
#define WW 56

// ---------------- scratch (module-static device memory; no allocs) ----------------
__device__ uint8_t g_ah[BB * HH * WW * CC];   // quantized high activations, NHWC uint8
__device__ uint8_t g_al[BB * HH * WW * CC];   // quantized low  activations, NHWC uint8
__device__ int8_t  g_wh[CC * 9 * CC];         // int8 weights [co][k][ci]
__device__ int8_t  g_wl[CC * 9 * CC];
__device__ float   g_fsh[CC];                 // fused scale: s_w_high[co] * act_scale_high
__device__ float   g_fsl[CC];

__device__ __forceinline__ int dp4a_us(unsigned a, unsigned b, int c) {
    int r;
    asm("dp4a.u32.s32 %0, %1, %2, %3;" : "=r"(r) : "r"(a), "r"(b), "r"(c));
    return r;
}

// ---------------- K1: per-output-channel weight quantization ----------------
// blockIdx.x = co. which==0 -> high(8b, n=127), which==1 -> low(4b, n=7)
__global__ __launch_bounds__(256) void quant_weights_kernel(
    const float* __restrict__ w, const float* __restrict__ as_ptr,
    float nlev, int which)
{
    int co = blockIdx.x;
    int tid = threadIdx.x;
    const float* wc = w + co * (CC * 9);
    int8_t* wq = which ? g_wl : g_wh;
    float*  fs = which ? g_fsl : g_fsh;

    float mx = 0.f;
    for (int i = tid; i < CC * 9; i += 256) mx = fmaxf(mx, fabsf(wc[i]));
    __shared__ float red[256];
    red[tid] = mx;
    __syncthreads();
    for (int s = 128; s > 0; s >>= 1) {
        if (tid < s) red[tid] = fmaxf(red[tid], red[tid + s]);
        __syncthreads();
    }
    float s = red[0] / nlev;

    for (int i = tid; i < CC * 9; i += 256) {
        float q = rintf(wc[i] / s);            // round-half-to-even, matches jnp.round
        q = fminf(fmaxf(q, -nlev), nlev);
        int ci = i / 9, k = i % 9;             // OIHW: i = ci*9 + (kh*3+kw)
        wq[(co * 9 + k) * CC + ci] = (int8_t)q;
    }
    if (tid == 0) fs[co] = s * as_ptr[0];
}

// ---------------- K2: predictor mask + activation fake-quant -> NHWC uint8 ----------------
// block = (bw, bh, b); handles one 8x8 spatial block across all 128 channels.
__global__ __launch_bounds__(256) void mask_quant_kernel(
    const float* __restrict__ x,
    const float* __restrict__ ash_p, const float* __restrict__ asl_p)
{
    int bw = blockIdx.x, bh = blockIdx.y, b = blockIdx.z;
    int tid = threadIdx.x;
    int h0 = bh * 8, w0 = bw * 8;

    __shared__ float sx[64][CC + 1];           // pixel-major, padded vs bank conflicts
    __shared__ uint8_t smask[CC];

    // coalesced load of the 8x8xC block (NCHW)
    for (int i = tid; i < 64 * CC; i += 256) {
        int c = i >> 6, p = i & 63;
        sx[p][c] = x[((b * CC + c) * HH + h0 + (p >> 3)) * WW + w0 + (p & 7)];
    }
    __syncthreads();

    // mask: avgpool8x8 >= 0.05, per channel. warp w handles 16 channels.
    int lane = tid & 31, wrp = tid >> 5;
    for (int j = 0; j < 16; j++) {
        int c = wrp * 16 + j;
        float v = sx[lane][c] + sx[lane + 32][c];
        #pragma unroll
        for (int o = 16; o > 0; o >>= 1) v += __shfl_xor_sync(0xffffffffu, v, o);
        if (lane == 0) smask[c] = (v * (1.0f / 64.0f) >= 0.05f) ? 1 : 0;
    }
    __syncthreads();

    float ash = ash_p[0], asl = asl_p[0];
    // quantize; EPS-filled side quantizes to exactly 0, so just zero it.
    for (int i = tid; i < 64 * (CC / 4); i += 256) {
        int p = i >> 5, c4 = (i & 31);
        int hh = h0 + (p >> 3), ww = w0 + (p & 7);
        unsigned qh = 0u, ql = 0u;
        #pragma unroll
        for (int j = 0; j < 4; j++) {
            int c = c4 * 4 + j;
            float v = sx[p][c];
            bool m = smask[c] != 0;
            float fh = fminf(fmaxf(rintf(v / ash), 0.f), 255.f);
            float fl = fminf(fmaxf(rintf(v / asl), 0.f), 15.f);
            unsigned b8h = m ? (unsigned)fh : 0u;
            unsigned b8l = m ? 0u : (unsigned)fl;
            qh |= b8h << (8 * j);
            ql |= b8l << (8 * j);
        }
        int base = ((b * HH + hh) * WW + ww) * (CC / 4) + c4;  // uint (4ch) units
        ((unsigned*)g_ah)[base] = qh;
        ((unsigned*)g_al)[base] = ql;
    }
}

// ---------------- K3: dual int8 conv3x3 (dp4a), exact integer accumulation ----------------
// CTA tile: 32 co x 8x8 pixels, one batch. 128 threads, each 4co x 4pix x 2 convs.
#define CO_TILE 32
#define SW_U4 (2 * CO_TILE * 9 * 8)   // 4608 uint4 = 73728 B  [t][co][k][g]
#define SA_U4 (2 * 8 * 100)           // 1600 uint4 = 25600 B  [t][g][pix(10x10)]
#define CONV_SMEM ((SW_U4 + SA_U4) * 16)

__global__ __launch_bounds__(128, 2) void conv_kernel(float* __restrict__ out)
{
    extern __shared__ uint4 smem[];
    uint4* s_w = smem;                 // [t][co][k][g]: ((t*32+co)*9+k)*8+g
    uint4* s_a = smem + SW_U4;         // [t][g][p]:     (t*8+g)*100+p

    int tid = threadIdx.x;
    int bz = blockIdx.z;
    int b   = bz >> 2;
    int co0 = (bz & 3) * CO_TILE;
    int h0 = blockIdx.y * 8, w0 = blockIdx.x * 8;

    // load weights (coalesced: consecutive i -> consecutive global uint4)
    for (int i = tid; i < SW_U4; i += 128) {
        int t  = i / (CO_TILE * 72);
        int r  = i % (CO_TILE * 72);
        int co = r / 72, kg = r % 72;
        const uint4* gw = t ? (const uint4*)g_wl : (const uint4*)g_wh;
        s_w[i] = gw[(co0 + co) * 72 + kg];
    }
    // load 10x10 activation tile with halo (zero padding)
    for (int i = tid; i < SA_U4; i += 128) {
        int t = i / 800, r = i % 800;
        int p = r >> 3, g = r & 7;
        int pr = p / 10 - 1 + h0;
        int pc = p % 10 - 1 + w0;
        uint4 v = make_uint4(0u, 0u, 0u, 0u);
        if (pr >= 0 && pr < HH && pc >= 0 && pc < WW) {
            const uint4* ga = t ? (const uint4*)g_al : (const uint4*)g_ah;
            v = ga[((b * HH + pr) * WW + pc) * 8 + g];
        }
        s_a[(t * 8 + g) * 100 + p] = v;
    }
    __syncthreads();

    int pg = tid & 15;     // pixel group: pixels pg + {0,16,32,48}
    int cg = tid >> 4;     // co group (0..7): co = co0 + cg*4 + j

    int acch[4][4], accl[4][4];
    #pragma unroll
    for (int j = 0; j < 4; j++)
        #pragma unroll
        for (int pp = 0; pp < 4; pp++) { acch[j][pp] = 0; accl[j][pp] = 0; }

    int pb[4];
    #pragma unroll
    for (int pp = 0; pp < 4; pp++) {
        int p = pg + 16 * pp;
        pb[pp] = (p >> 3) * 10 + (p & 7);
    }

    #pragma unroll 1
    for (int kh = 0; kh < 3; kh++) {
        #pragma unroll 1
        for (int kw = 0; kw < 3; kw++) {
            int k = kh * 3 + kw;
            int off = kh * 10 + kw;
            const uint4* wb = s_w + ((cg * 4) * 9 + k) * 8;
            #pragma unroll
            for (int g = 0; g < 8; g++) {
                uint4 ah[4], al[4];
                #pragma unroll
                for (int pp = 0; pp < 4; pp++) {
                    int pin = pb[pp] + off;
                    ah[pp] = s_a[g * 100 + pin];
                    al[pp] = s_a[800 + g * 100 + pin];
                }
                #pragma unroll
                for (int j = 0; j < 4; j++) {
                    uint4 wh = wb[j * 72 + g];
                    uint4 wl = wb[CO_TILE * 72 + j * 72 + g];
                    #pragma unroll
                    for (int pp = 0; pp < 4; pp++) {
                        acch[j][pp] = dp4a_us(ah[pp].x, wh.x, acch[j][pp]);
                        acch[j][pp] = dp4a_us(ah[pp].y, wh.y, acch[j][pp]);
                        acch[j][pp] = dp4a_us(ah[pp].z, wh.z, acch[j][pp]);
                        acch[j][pp] = dp4a_us(ah[pp].w, wh.w, acch[j][pp]);
                        accl[j][pp] = dp4a_us(al[pp].x, wl.x, accl[j][pp]);
                        accl[j][pp] = dp4a_us(al[pp].y, wl.y, accl[j][pp]);
                        accl[j][pp] = dp4a_us(al[pp].z, wl.z, accl[j][pp]);
                        accl[j][pp] = dp4a_us(al[pp].w, wl.w, accl[j][pp]);
                    }
                }
            }
        }
    }

    // epilogue: y = fsh[co]*acc_h + fsl[co]*acc_l  (NCHW fp32)
    #pragma unroll
    for (int j = 0; j < 4; j++) {
        int co = co0 + cg * 4 + j;
        float sh = g_fsh[co];
        float sl = g_fsl[co];
        #pragma unroll
        for (int pp = 0; pp < 4; pp++) {
            int p = pg + 16 * pp;
            int oh = h0 + (p >> 3), ow = w0 + (p & 7);
            out[((b * CC + co) * HH + oh) * WW + ow] =
                sh * (float)acch[j][pp] + sl * (float)accl[j][pp];
        }
    }
}

// ---------------- launch ----------------
extern "C" void kernel_launch(void* const* d_in, const int* in_sizes, int n_in,
                              void* d_out, int out_size)
{
    const float* x      = (const float*)d_in[0];
    const float* w_high = (const float*)d_in[1];
    const float* w_low  = (const float*)d_in[2];
    const float* as_h   = (const float*)d_in[3];
    const float* as_l   = (const float*)d_in[4];
    float* out = (float*)d_out;

    cudaFuncSetAttribute(conv_kernel,
                         cudaFuncAttributeMaxDynamicSharedMemorySize, CONV_SMEM);

    quant_weights_kernel<<<CC, 256>>>(w_high, as_h, 127.0f, 0);
    quant_weights_kernel<<<CC, 256>>>(w_low,  as_l,   7.0f, 1);
    mask_quant_kernel<<<dim3(WW / 8, HH / 8, BB), 256>>>(x, as_h, as_l);
    conv_kernel<<<dim3(WW / 8, HH / 8, BB * (CC / CO_TILE)), 128, CONV_SMEM>>>(out);
}

// round 2
// speedup vs baseline: 1.0906x; 1.0906x over previous
#include <cuda_runtime.h>
#include <cstdint>

#define BB 32
#define CC 128
#define HH 56
#define WW 56

// ---------------- scratch (module-static device memory; no allocs) ----------------
__device__ uint8_t g_ah[BB * HH * WW * CC];   // quantized high activations, NHWC uint8
__device__ uint8_t g_al[BB * HH * WW * CC];   // quantized low  activations, NHWC uint8
__device__ int8_t  g_wh[CC * 9 * CC];         // int8 weights [co][k][ci]
__device__ int8_t  g_wl[CC * 9 * CC];
__device__ float   g_fsh[CC];                 // fused scale: s_w_high[co] * act_scale_high
__device__ float   g_fsl[CC];

// ---------------- K1: per-output-channel weight quantization ----------------
__global__ __launch_bounds__(256) void quant_weights_kernel(
    const float* __restrict__ w, const float* __restrict__ as_ptr,
    float nlev, int which)
{
    int co = blockIdx.x;
    int tid = threadIdx.x;
    const float* wc = w + co * (CC * 9);
    int8_t* wq = which ? g_wl : g_wh;
    float*  fs = which ? g_fsl : g_fsh;

    float mx = 0.f;
    for (int i = tid; i < CC * 9; i += 256) mx = fmaxf(mx, fabsf(wc[i]));
    __shared__ float red[256];
    red[tid] = mx;
    __syncthreads();
    for (int s = 128; s > 0; s >>= 1) {
        if (tid < s) red[tid] = fmaxf(red[tid], red[tid + s]);
        __syncthreads();
    }
    float s = red[0] / nlev;

    for (int i = tid; i < CC * 9; i += 256) {
        float q = rintf(wc[i] / s);
        q = fminf(fmaxf(q, -nlev), nlev);
        int ci = i / 9, k = i % 9;             // OIHW: i = ci*9 + (kh*3+kw)
        wq[(co * 9 + k) * CC + ci] = (int8_t)q;
    }
    if (tid == 0) fs[co] = s * as_ptr[0];
}

// ---------------- K2: predictor mask + activation fake-quant -> NHWC uint8 ----------------
__global__ __launch_bounds__(256) void mask_quant_kernel(
    const float* __restrict__ x,
    const float* __restrict__ ash_p, const float* __restrict__ asl_p)
{
    int bw = blockIdx.x, bh = blockIdx.y, b = blockIdx.z;
    int tid = threadIdx.x;
    int h0 = bh * 8, w0 = bw * 8;

    __shared__ float sx[64][CC + 1];
    __shared__ uint8_t smask[CC];

    for (int i = tid; i < 64 * CC; i += 256) {
        int c = i >> 6, p = i & 63;
        sx[p][c] = x[((b * CC + c) * HH + h0 + (p >> 3)) * WW + w0 + (p & 7)];
    }
    __syncthreads();

    int lane = tid & 31, wrp = tid >> 5;
    for (int j = 0; j < 16; j++) {
        int c = wrp * 16 + j;
        float v = sx[lane][c] + sx[lane + 32][c];
        #pragma unroll
        for (int o = 16; o > 0; o >>= 1) v += __shfl_xor_sync(0xffffffffu, v, o);
        if (lane == 0) smask[c] = (v * (1.0f / 64.0f) >= 0.05f) ? 1 : 0;
    }
    __syncthreads();

    float ash = ash_p[0], asl = asl_p[0];
    for (int i = tid; i < 64 * (CC / 4); i += 256) {
        int p = i >> 5, c4 = (i & 31);
        int hh = h0 + (p >> 3), ww = w0 + (p & 7);
        unsigned qh = 0u, ql = 0u;
        #pragma unroll
        for (int j = 0; j < 4; j++) {
            int c = c4 * 4 + j;
            float v = sx[p][c];
            bool m = smask[c] != 0;
            float fh = fminf(fmaxf(rintf(v / ash), 0.f), 255.f);
            float fl = fminf(fmaxf(rintf(v / asl), 0.f), 15.f);
            unsigned b8h = m ? (unsigned)fh : 0u;
            unsigned b8l = m ? 0u : (unsigned)fl;
            qh |= b8h << (8 * j);
            ql |= b8l << (8 * j);
        }
        int base = ((b * HH + hh) * WW + ww) * (CC / 4) + c4;
        ((unsigned*)g_ah)[base] = qh;
        ((unsigned*)g_al)[base] = ql;
    }
}

// ---------------- K3: dual int8 conv3x3 via tensor-core MMA ----------------
// CTA: 64 pixels (8x8) x 128 co x 2 convs. 8 warps (2M x 4N), warp = 32pix x 32co.
// mma.sync.m16n8k32 u8 x s8 -> s32, exact integer accumulation.

#define ROWB 144                                // padded row stride (conflict-free)
#define ACT_CONV_STRIDE (100 * ROWB)            // 10x10 halo pixels
#define ACT_BYTES (2 * ACT_CONV_STRIDE)         // 28800
#define WCONV_STRIDE (CC * ROWB)                // 18432
#define WBUF_BYTES (2 * WCONV_STRIDE)           // 36864 per stage (both convs)
#define CONV_SMEM (ACT_BYTES + 2 * WBUF_BYTES)  // 102528 (double-buffered weights)

__device__ __forceinline__ void mma_u8s8(int* c, const unsigned* a, unsigned b0, unsigned b1) {
    asm volatile(
        "mma.sync.aligned.m16n8k32.row.col.s32.u8.s8.s32 "
        "{%0,%1,%2,%3}, {%4,%5,%6,%7}, {%8,%9}, {%0,%1,%2,%3};"
        : "+r"(c[0]), "+r"(c[1]), "+r"(c[2]), "+r"(c[3])
        : "r"(a[0]), "r"(a[1]), "r"(a[2]), "r"(a[3]), "r"(b0), "r"(b1));
}

__device__ __forceinline__ void stage_weights(char* dstbase, int k, int tid) {
    unsigned sdst = (unsigned)__cvta_generic_to_shared(dstbase);
    #pragma unroll
    for (int j = 0; j < 8; j++) {
        int i = tid + j * 256;                   // 2048 chunks of 16B
        int cv = i >> 10, r = i & 1023;
        int co = r >> 3, c16 = r & 7;
        const char* src = (cv ? (const char*)g_wl : (const char*)g_wh)
                          + (co * 9 + k) * CC + c16 * 16;
        unsigned d = sdst + cv * WCONV_STRIDE + co * ROWB + c16 * 16;
        asm volatile("cp.async.cg.shared.global [%0], [%1], 16;" :: "r"(d), "l"(src));
    }
}

__global__ __launch_bounds__(256, 2) void conv_mma_kernel(float* __restrict__ out)
{
    extern __shared__ char smem[];
    char* s_act = smem;                          // [conv][pin(100)][144B]
    char* s_w   = smem + ACT_BYTES;              // [buf][conv][co(128)][144B]

    int tid = threadIdx.x;
    int b = blockIdx.z;
    int h0 = blockIdx.y * 8, w0 = blockIdx.x * 8;

    // preload activation halo tiles (both convs), NHWC 128B/pixel -> 144B rows
    #pragma unroll
    for (int j = 0; j < 7; j++) {
        int i = tid + j * 256;                   // 1600 uint4 total
        if (i < 1600) {
            int cv = i / 800, r = i % 800;
            int p = r >> 3, c16 = r & 7;
            int pr = p / 10 - 1 + h0, pc = p % 10 - 1 + w0;
            uint4 v = make_uint4(0u, 0u, 0u, 0u);
            if (pr >= 0 && pr < HH && pc >= 0 && pc < WW) {
                const uint4* ga = cv ? (const uint4*)g_al : (const uint4*)g_ah;
                v = ga[((b * HH + pr) * WW + pc) * 8 + c16];
            }
            *(uint4*)(s_act + cv * ACT_CONV_STRIDE + p * ROWB + c16 * 16) = v;
        }
    }

    stage_weights(s_w, 0, tid);
    asm volatile("cp.async.commit_group;" ::: "memory");

    int lane = tid & 31, warp = tid >> 5;
    int warpM = warp >> 2;       // 0..1 : 32-pixel half
    int warpN = warp & 3;        // 0..3 : 32-co group
    int g = lane >> 2, t = lane & 3;

    int acc[2][2][4][4];         // [conv][mtile][ntile][c0..c3]
    #pragma unroll
    for (int cv = 0; cv < 2; cv++)
        #pragma unroll
        for (int mt = 0; mt < 2; mt++)
            #pragma unroll
            for (int nt = 0; nt < 4; nt++)
                #pragma unroll
                for (int q = 0; q < 4; q++) acc[cv][mt][nt][q] = 0;

    // pixel coords: p = warpM*32 + mt*16 + hf*8 + g  (base multiple of 8 -> pw = g)
    int phh[2][2];
    #pragma unroll
    for (int mt = 0; mt < 2; mt++)
        #pragma unroll
        for (int hf = 0; hf < 2; hf++)
            phh[mt][hf] = (warpM * 32 + mt * 16 + hf * 8 + g) >> 3;

    #pragma unroll 1
    for (int k9 = 0; k9 < 9; k9++) {
        asm volatile("cp.async.wait_group 0;" ::: "memory");
        __syncthreads();
        char* wcur = s_w + (k9 & 1) * WBUF_BYTES;
        if (k9 < 8) {
            stage_weights(s_w + ((k9 + 1) & 1) * WBUF_BYTES, k9 + 1, tid);
            asm volatile("cp.async.commit_group;" ::: "memory");
        }
        int kh = k9 / 3, kw = k9 - kh * 3;
        int pin[2][2];
        #pragma unroll
        for (int mt = 0; mt < 2; mt++)
            #pragma unroll
            for (int hf = 0; hf < 2; hf++)
                pin[mt][hf] = (phh[mt][hf] + kh) * 10 + g + kw;

        #pragma unroll
        for (int chunk = 0; chunk < 4; chunk++) {
            unsigned a[2][2][4];
            #pragma unroll
            for (int cv = 0; cv < 2; cv++) {
                const char* base = s_act + cv * ACT_CONV_STRIDE + chunk * 32 + t * 4;
                #pragma unroll
                for (int mt = 0; mt < 2; mt++) {
                    a[cv][mt][0] = *(const unsigned*)(base + pin[mt][0] * ROWB);
                    a[cv][mt][1] = *(const unsigned*)(base + pin[mt][1] * ROWB);
                    a[cv][mt][2] = *(const unsigned*)(base + pin[mt][0] * ROWB + 16);
                    a[cv][mt][3] = *(const unsigned*)(base + pin[mt][1] * ROWB + 16);
                }
            }
            #pragma unroll
            for (int cv = 0; cv < 2; cv++) {
                const char* wb0 = wcur + cv * WCONV_STRIDE + chunk * 32 + t * 4;
                #pragma unroll
                for (int nt = 0; nt < 4; nt++) {
                    int co = warpN * 32 + nt * 8 + g;
                    const char* wb = wb0 + co * ROWB;
                    unsigned b0 = *(const unsigned*)wb;
                    unsigned b1 = *(const unsigned*)(wb + 16);
                    #pragma unroll
                    for (int mt = 0; mt < 2; mt++)
                        mma_u8s8(acc[cv][mt][nt], a[cv][mt], b0, b1);
                }
            }
        }
    }

    // epilogue: y = fsh[co]*acc_h + fsl[co]*acc_l  -> NCHW fp32
    #pragma unroll
    for (int nt = 0; nt < 4; nt++) {
        int co0 = warpN * 32 + nt * 8 + t * 2;
        float sh0 = g_fsh[co0],     sl0 = g_fsl[co0];
        float sh1 = g_fsh[co0 + 1], sl1 = g_fsl[co0 + 1];
        #pragma unroll
        for (int mt = 0; mt < 2; mt++) {
            #pragma unroll
            for (int hf = 0; hf < 2; hf++) {
                int p = warpM * 32 + mt * 16 + hf * 8 + g;
                int oh = h0 + (p >> 3), ow = w0 + (p & 7);
                int q = hf * 2;
                float y0 = sh0 * (float)acc[0][mt][nt][q]     + sl0 * (float)acc[1][mt][nt][q];
                float y1 = sh1 * (float)acc[0][mt][nt][q + 1] + sl1 * (float)acc[1][mt][nt][q + 1];
                out[((b * CC + co0) * HH + oh) * WW + ow] = y0;
                out[((b * CC + co0 + 1) * HH + oh) * WW + ow] = y1;
            }
        }
    }
}

// ---------------- launch ----------------
extern "C" void kernel_launch(void* const* d_in, const int* in_sizes, int n_in,
                              void* d_out, int out_size)
{
    const float* x      = (const float*)d_in[0];
    const float* w_high = (const float*)d_in[1];
    const float* w_low  = (const float*)d_in[2];
    const float* as_h   = (const float*)d_in[3];
    const float* as_l   = (const float*)d_in[4];
    float* out = (float*)d_out;

    cudaFuncSetAttribute(conv_mma_kernel,
                         cudaFuncAttributeMaxDynamicSharedMemorySize, CONV_SMEM);

    quant_weights_kernel<<<CC, 256>>>(w_high, as_h, 127.0f, 0);
    quant_weights_kernel<<<CC, 256>>>(w_low,  as_l,   7.0f, 1);
    mask_quant_kernel<<<dim3(WW / 8, HH / 8, BB), 256>>>(x, as_h, as_l);
    conv_mma_kernel<<<dim3(WW / 8, HH / 8, BB), 256, CONV_SMEM>>>(out);
}

// round 3
// speedup vs baseline: 1.0914x; 1.0007x over previous
#include <cuda_runtime.h>
#include <cstdint>

#define BB 32
#define CC 128
#define HH 56
#define WW 56

// ---------------- scratch (module-static device memory; no allocs) ----------------
__device__ uint8_t g_ah[BB * HH * WW * CC];   // quantized high activations, NHWC uint8
__device__ uint8_t g_al[BB * HH * WW * CC];   // quantized low  activations, NHWC uint8
__device__ int8_t  g_wh[CC * 9 * CC];         // int8 weights [co][k][ci]
__device__ int8_t  g_wl[CC * 9 * CC];
__device__ float   g_fsh[CC];                 // fused scale: s_w_high[co] * act_scale_high
__device__ float   g_fsl[CC];

// ---------------- K1: per-output-channel weight quantization ----------------
__global__ __launch_bounds__(256) void quant_weights_kernel(
    const float* __restrict__ w, const float* __restrict__ as_ptr,
    float nlev, int which)
{
    int co = blockIdx.x;
    int tid = threadIdx.x;
    const float* wc = w + co * (CC * 9);
    int8_t* wq = which ? g_wl : g_wh;
    float*  fs = which ? g_fsl : g_fsh;

    float mx = 0.f;
    for (int i = tid; i < CC * 9; i += 256) mx = fmaxf(mx, fabsf(wc[i]));
    __shared__ float red[256];
    red[tid] = mx;
    __syncthreads();
    for (int s = 128; s > 0; s >>= 1) {
        if (tid < s) red[tid] = fmaxf(red[tid], red[tid + s]);
        __syncthreads();
    }
    float s = red[0] / nlev;

    for (int i = tid; i < CC * 9; i += 256) {
        float q = rintf(wc[i] / s);
        q = fminf(fmaxf(q, -nlev), nlev);
        int ci = i / 9, k = i % 9;             // OIHW: i = ci*9 + (kh*3+kw)
        wq[(co * 9 + k) * CC + ci] = (int8_t)q;
    }
    if (tid == 0) fs[co] = s * as_ptr[0];
}

// ---------------- K2: predictor mask + activation fake-quant -> NHWC uint8 ----------------
__global__ __launch_bounds__(256) void mask_quant_kernel(
    const float* __restrict__ x,
    const float* __restrict__ ash_p, const float* __restrict__ asl_p)
{
    int bw = blockIdx.x, bh = blockIdx.y, b = blockIdx.z;
    int tid = threadIdx.x;
    int h0 = bh * 8, w0 = bw * 8;

    __shared__ float sx[64][CC + 1];
    __shared__ uint8_t smask[CC];

    for (int i = tid; i < 64 * CC; i += 256) {
        int c = i >> 6, p = i & 63;
        sx[p][c] = x[((b * CC + c) * HH + h0 + (p >> 3)) * WW + w0 + (p & 7)];
    }
    __syncthreads();

    int lane = tid & 31, wrp = tid >> 5;
    for (int j = 0; j < 16; j++) {
        int c = wrp * 16 + j;
        float v = sx[lane][c] + sx[lane + 32][c];
        #pragma unroll
        for (int o = 16; o > 0; o >>= 1) v += __shfl_xor_sync(0xffffffffu, v, o);
        if (lane == 0) smask[c] = (v * (1.0f / 64.0f) >= 0.05f) ? 1 : 0;
    }
    __syncthreads();

    float ash = ash_p[0], asl = asl_p[0];
    for (int i = tid; i < 64 * (CC / 4); i += 256) {
        int p = i >> 5, c4 = (i & 31);
        int hh = h0 + (p >> 3), ww = w0 + (p & 7);
        unsigned qh = 0u, ql = 0u;
        #pragma unroll
        for (int j = 0; j < 4; j++) {
            int c = c4 * 4 + j;
            float v = sx[p][c];
            bool m = smask[c] != 0;
            float fh = fminf(fmaxf(rintf(v / ash), 0.f), 255.f);
            float fl = fminf(fmaxf(rintf(v / asl), 0.f), 15.f);
            unsigned b8h = m ? (unsigned)fh : 0u;
            unsigned b8l = m ? 0u : (unsigned)fl;
            qh |= b8h << (8 * j);
            ql |= b8l << (8 * j);
        }
        int base = ((b * HH + hh) * WW + ww) * (CC / 4) + c4;
        ((unsigned*)g_ah)[base] = qh;
        ((unsigned*)g_al)[base] = ql;
    }
}

// ---------------- K3: dual int8 conv3x3 via tensor-core MMA ----------------
// CTA: 64 pixels (8x8) x 128 co x 2 convs. 8 warps (2M x 4N), warp = 32pix x 32co.
// mma.sync.m16n8k32 u8 x s8 -> s32, exact integer accumulation.

#define ROWB 144                                // padded row stride (conflict-free)
#define ACT_CONV_STRIDE (100 * ROWB)            // 10x10 halo pixels
#define ACT_BYTES (2 * ACT_CONV_STRIDE)         // 28800
#define WCONV_STRIDE (CC * ROWB)                // 18432
#define WBUF_BYTES (2 * WCONV_STRIDE)           // 36864 per stage (both convs)
#define CONV_SMEM (ACT_BYTES + 2 * WBUF_BYTES)  // 102528 (double-buffered weights)

__device__ __forceinline__ void mma_u8s8(int* c, const unsigned* a, unsigned b0, unsigned b1) {
    asm volatile(
        "mma.sync.aligned.m16n8k32.row.col.s32.u8.s8.s32 "
        "{%0,%1,%2,%3}, {%4,%5,%6,%7}, {%8,%9}, {%0,%1,%2,%3};"
        : "+r"(c[0]), "+r"(c[1]), "+r"(c[2]), "+r"(c[3])
        : "r"(a[0]), "r"(a[1]), "r"(a[2]), "r"(a[3]), "r"(b0), "r"(b1));
}

__device__ __forceinline__ void stage_weights(char* dstbase, int k, int tid) {
    unsigned sdst = (unsigned)__cvta_generic_to_shared(dstbase);
    #pragma unroll
    for (int j = 0; j < 8; j++) {
        int i = tid + j * 256;                   // 2048 chunks of 16B
        int cv = i >> 10, r = i & 1023;
        int co = r >> 3, c16 = r & 7;
        const char* src = (cv ? (const char*)g_wl : (const char*)g_wh)
                          + (co * 9 + k) * CC + c16 * 16;
        unsigned d = sdst + cv * WCONV_STRIDE + co * ROWB + c16 * 16;
        asm volatile("cp.async.cg.shared.global [%0], [%1], 16;" :: "r"(d), "l"(src));
    }
}

__global__ __launch_bounds__(256, 2) void conv_mma_kernel(float* __restrict__ out)
{
    extern __shared__ char smem[];
    char* s_act = smem;                          // [conv][pin(100)][144B]
    char* s_w   = smem + ACT_BYTES;              // [buf][conv][co(128)][144B]

    int tid = threadIdx.x;
    int b = blockIdx.z;
    int h0 = blockIdx.y * 8, w0 = blockIdx.x * 8;

    // preload activation halo tiles (both convs), NHWC 128B/pixel -> 144B rows
    #pragma unroll
    for (int j = 0; j < 7; j++) {
        int i = tid + j * 256;                   // 1600 uint4 total
        if (i < 1600) {
            int cv = i / 800, r = i % 800;
            int p = r >> 3, c16 = r & 7;
            int pr = p / 10 - 1 + h0, pc = p % 10 - 1 + w0;
            uint4 v = make_uint4(0u, 0u, 0u, 0u);
            if (pr >= 0 && pr < HH && pc >= 0 && pc < WW) {
                const uint4* ga = cv ? (const uint4*)g_al : (const uint4*)g_ah;
                v = ga[((b * HH + pr) * WW + pc) * 8 + c16];
            }
            *(uint4*)(s_act + cv * ACT_CONV_STRIDE + p * ROWB + c16 * 16) = v;
        }
    }

    stage_weights(s_w, 0, tid);
    asm volatile("cp.async.commit_group;" ::: "memory");

    int lane = tid & 31, warp = tid >> 5;
    int warpM = warp >> 2;       // 0..1 : 32-pixel half
    int warpN = warp & 3;        // 0..3 : 32-co group
    int g = lane >> 2, t = lane & 3;

    int acc[2][2][4][4];         // [conv][mtile][ntile][c0..c3]
    #pragma unroll
    for (int cv = 0; cv < 2; cv++)
        #pragma unroll
        for (int mt = 0; mt < 2; mt++)
            #pragma unroll
            for (int nt = 0; nt < 4; nt++)
                #pragma unroll
                for (int q = 0; q < 4; q++) acc[cv][mt][nt][q] = 0;

    // pixel coords: p = warpM*32 + mt*16 + hf*8 + g  (base multiple of 8 -> pw = g)
    int phh[2][2];
    #pragma unroll
    for (int mt = 0; mt < 2; mt++)
        #pragma unroll
        for (int hf = 0; hf < 2; hf++)
            phh[mt][hf] = (warpM * 32 + mt * 16 + hf * 8 + g) >> 3;

    #pragma unroll 1
    for (int k9 = 0; k9 < 9; k9++) {
        asm volatile("cp.async.wait_group 0;" ::: "memory");
        __syncthreads();
        char* wcur = s_w + (k9 & 1) * WBUF_BYTES;
        if (k9 < 8) {
            stage_weights(s_w + ((k9 + 1) & 1) * WBUF_BYTES, k9 + 1, tid);
            asm volatile("cp.async.commit_group;" ::: "memory");
        }
        int kh = k9 / 3, kw = k9 - kh * 3;
        int pin[2][2];
        #pragma unroll
        for (int mt = 0; mt < 2; mt++)
            #pragma unroll
            for (int hf = 0; hf < 2; hf++)
                pin[mt][hf] = (phh[mt][hf] + kh) * 10 + g + kw;

        #pragma unroll
        for (int chunk = 0; chunk < 4; chunk++) {
            unsigned a[2][2][4];
            #pragma unroll
            for (int cv = 0; cv < 2; cv++) {
                const char* base = s_act + cv * ACT_CONV_STRIDE + chunk * 32 + t * 4;
                #pragma unroll
                for (int mt = 0; mt < 2; mt++) {
                    a[cv][mt][0] = *(const unsigned*)(base + pin[mt][0] * ROWB);
                    a[cv][mt][1] = *(const unsigned*)(base + pin[mt][1] * ROWB);
                    a[cv][mt][2] = *(const unsigned*)(base + pin[mt][0] * ROWB + 16);
                    a[cv][mt][3] = *(const unsigned*)(base + pin[mt][1] * ROWB + 16);
                }
            }
            #pragma unroll
            for (int cv = 0; cv < 2; cv++) {
                const char* wb0 = wcur + cv * WCONV_STRIDE + chunk * 32 + t * 4;
                #pragma unroll
                for (int nt = 0; nt < 4; nt++) {
                    int co = warpN * 32 + nt * 8 + g;
                    const char* wb = wb0 + co * ROWB;
                    unsigned b0 = *(const unsigned*)wb;
                    unsigned b1 = *(const unsigned*)(wb + 16);
                    #pragma unroll
                    for (int mt = 0; mt < 2; mt++)
                        mma_u8s8(acc[cv][mt][nt], a[cv][mt], b0, b1);
                }
            }
        }
    }

    // epilogue: y = fsh[co]*acc_h + fsl[co]*acc_l  -> NCHW fp32
    #pragma unroll
    for (int nt = 0; nt < 4; nt++) {
        int co0 = warpN * 32 + nt * 8 + t * 2;
        float sh0 = g_fsh[co0],     sl0 = g_fsl[co0];
        float sh1 = g_fsh[co0 + 1], sl1 = g_fsl[co0 + 1];
        #pragma unroll
        for (int mt = 0; mt < 2; mt++) {
            #pragma unroll
            for (int hf = 0; hf < 2; hf++) {
                int p = warpM * 32 + mt * 16 + hf * 8 + g;
                int oh = h0 + (p >> 3), ow = w0 + (p & 7);
                int q = hf * 2;
                float y0 = sh0 * (float)acc[0][mt][nt][q]     + sl0 * (float)acc[1][mt][nt][q];
                float y1 = sh1 * (float)acc[0][mt][nt][q + 1] + sl1 * (float)acc[1][mt][nt][q + 1];
                out[((b * CC + co0) * HH + oh) * WW + ow] = y0;
                out[((b * CC + co0 + 1) * HH + oh) * WW + ow] = y1;
            }
        }
    }
}

// ---------------- launch ----------------
extern "C" void kernel_launch(void* const* d_in, const int* in_sizes, int n_in,
                              void* d_out, int out_size)
{
    const float* x      = (const float*)d_in[0];
    const float* w_high = (const float*)d_in[1];
    const float* w_low  = (const float*)d_in[2];
    const float* as_h   = (const float*)d_in[3];
    const float* as_l   = (const float*)d_in[4];
    float* out = (float*)d_out;

    cudaFuncSetAttribute(conv_mma_kernel,
                         cudaFuncAttributeMaxDynamicSharedMemorySize, CONV_SMEM);

    quant_weights_kernel<<<CC, 256>>>(w_high, as_h, 127.0f, 0);
    quant_weights_kernel<<<CC, 256>>>(w_low,  as_l,   7.0f, 1);
    mask_quant_kernel<<<dim3(WW / 8, HH / 8, BB), 256>>>(x, as_h, as_l);
    conv_mma_kernel<<<dim3(WW / 8, HH / 8, BB), 256, CONV_SMEM>>>(out);
}